// round 4
// baseline (speedup 1.0000x reference)
#include <cuda_runtime.h>
#include <math.h>

#define N_ITEMS 200000
#define N_USERS 100000
#define N_INTER 2000000
#define GCN 64
#define HID 256
#define TOW 128

typedef unsigned long long u64;

// packed dual-FMA: (d.lo,d.hi) += (a.lo*b.lo, a.hi*b.hi)
#define FMA2(d, a, b) \
    asm("fma.rn.f32x2 %0, %1, %2, %0;" : "+l"(d) : "l"(a), "l"(b))

#define UNPACK2(lo, hi, p) \
    asm("mov.b64 {%0, %1}, %2;" : "=f"(lo), "=f"(hi) : "l"(p))

// ---------------- scratch (static device globals; no runtime alloc) ----------
__device__ float g_item_emb[(size_t)N_ITEMS * TOW];      // 102.4 MB
__device__ float g_H[(size_t)N_ITEMS * HID];             // 204.8 MB (reused by user tower)
__device__ float g_fused[(size_t)N_USERS * (GCN + TOW)]; // 76.8 MB
__device__ int   g_start[N_USERS];
__device__ int   g_end[N_USERS];

// padded K stride: multiple of 4 words AND ≡4 (mod 8) so 8-lane LDS.128 phases
// are bank-conflict-free (stride*4 words per lane covers all 32 banks).
template <int K> struct PadK {
    static constexpr int a = (K + 3) & ~3;
    static constexpr int value = (a % 8 == 4) ? a : a + 4;
};

// ---------------------------------------------------------------------------
// Fused layer: Y = post( X @ W + b ),  X = concat(X1[:k1], X2[:K-k1])
//  - W transposed into SMEM as Wt[N][K4] once per CTA (persistent CTAs)
//  - 256 threads = 4 row-groups x 64 col-lanes
//  - per-thread register tile: R rows x C cols, accumulated as f32x2 packed
//    along k (k, k+1) -> both operands naturally packed from LDS.128
//  - RELU: bias+relu+store.  L2N (N==128): per-row cross-warp L2 normalize.
// ---------------------------------------------------------------------------
template <int K, int N, bool RELU, bool L2N>
__global__ void __launch_bounds__(256, 1)
gemm_kernel(const float* __restrict__ X1, int k1,
            const float* __restrict__ X2,
            const float* __restrict__ W,
            const float* __restrict__ bias,
            float* __restrict__ Y, int M)
{
    constexpr int K4 = PadK<K>::value;
    constexpr int C  = N / 64;             // cols per thread (2 or 4)
    constexpr int R  = 32 / C;             // rows per thread (16 or 8)
    constexpr int TR = 4 * R;              // tile rows (64 or 32)
    constexpr int NG = K4 / 4;             // 4-k groups

    extern __shared__ float sm[];
    float* Ws = sm;                        // [N][K4] transposed weights
    float* Xs = sm + (size_t)N * K4;       // [TR][K4]
    float* Sr = Xs + (size_t)TR * K4;      // [8][R] row ssq partials (L2N)

    const int tid = threadIdx.x;
    const int ty = tid >> 6;               // 0..3
    const int tx = tid & 63;               // 0..63
    const int warp = tid >> 5;
    const int lane = tid & 31;

    // Stage transposed weights once (strided global reads -> coalesced STS).
    for (int i = tid; i < N * K4; i += 256) {
        int n = i / K4, k = i - n * K4;
        Ws[i] = (k < K) ? W[k * N + n] : 0.f;
    }

    float breg[C];
#pragma unroll
    for (int j = 0; j < C; ++j) breg[j] = bias[tx + 64 * j];

    const ulonglong2* wp[C];
#pragma unroll
    for (int j = 0; j < C; ++j)
        wp[j] = reinterpret_cast<const ulonglong2*>(Ws + (size_t)(tx + 64 * j) * K4);
    const ulonglong2* xp[R];
#pragma unroll
    for (int i = 0; i < R; ++i)
        xp[i] = reinterpret_cast<const ulonglong2*>(Xs + (size_t)(ty + 4 * i) * K4);

    const int ntiles = (M + TR - 1) / TR;
    for (int tile = blockIdx.x; tile < ntiles; tile += gridDim.x) {
        const int row0 = tile * TR;
        __syncthreads();   // protect Xs/Sr from previous iteration (and W load, 1st)

        // Stage X tile [TR x K4] with concat, tail guard, zero pad.
        for (int i = tid; i < TR * K4; i += 256) {
            int r = i / K4, c = i - r * K4;
            int gr = row0 + r;
            float v = 0.f;
            if (gr < M && c < K)
                v = (c < k1) ? X1[(size_t)gr * k1 + c]
                             : X2[(size_t)gr * (K - k1) + (c - k1)];
            Xs[i] = v;
        }
        __syncthreads();

        u64 acc[R][C];
#pragma unroll
        for (int i = 0; i < R; ++i)
#pragma unroll
            for (int j = 0; j < C; ++j) acc[i][j] = 0ull;

#pragma unroll 2
        for (int g = 0; g < NG; ++g) {
            ulonglong2 w[C];
#pragma unroll
            for (int j = 0; j < C; ++j) w[j] = wp[j][g];
#pragma unroll
            for (int i = 0; i < R; ++i) {
                ulonglong2 a = xp[i][g];   // broadcast within warp
#pragma unroll
                for (int j = 0; j < C; ++j) {
                    FMA2(acc[i][j], a.x, w[j].x);
                    FMA2(acc[i][j], a.y, w[j].y);
                }
            }
        }

        // unpack + bias
        float val[R][C];
#pragma unroll
        for (int i = 0; i < R; ++i)
#pragma unroll
            for (int j = 0; j < C; ++j) {
                float lo, hi;
                UNPACK2(lo, hi, acc[i][j]);
                val[i][j] = lo + hi + breg[j];
            }

        if (RELU) {
#pragma unroll
            for (int i = 0; i < R; ++i) {
                int gr = row0 + ty + 4 * i;
                if (gr < M) {
#pragma unroll
                    for (int j = 0; j < C; ++j)
                        Y[(size_t)gr * N + tx + 64 * j] = fmaxf(val[i][j], 0.f);
                }
            }
        } else {   // L2N, N==128, C==2
            // per-warp partial sum of squares per row, then combine warp pair
            float ssq[R];
#pragma unroll
            for (int i = 0; i < R; ++i) {
                float s = val[i][0] * val[i][0] + val[i][1] * val[i][1];
#pragma unroll
                for (int o = 16; o > 0; o >>= 1)
                    s += __shfl_xor_sync(0xffffffffu, s, o);
                ssq[i] = s;
            }
            if (lane == 0) {
#pragma unroll
                for (int i = 0; i < R; ++i) Sr[warp * R + i] = ssq[i];
            }
            __syncthreads();
#pragma unroll
            for (int i = 0; i < R; ++i) {
                float tot = Sr[warp * R + i] + Sr[(warp ^ 1) * R + i];
                float scale = 1.0f / fmaxf(sqrtf(tot), 1e-12f);
                int gr = row0 + ty + 4 * i;
                if (gr < M) {
                    Y[(size_t)gr * 128 + tx]      = val[i][0] * scale;
                    Y[(size_t)gr * 128 + tx + 64] = val[i][1] * scale;
                }
            }
        }
    }
}

// ---------------------------------------------------------------------------
// Segment boundaries from sorted seg_ids (users with no interactions -> [0,0))
// ---------------------------------------------------------------------------
__global__ void bounds_init_kernel(int* __restrict__ s, int* __restrict__ e, int n)
{
    int i = blockIdx.x * blockDim.x + threadIdx.x;
    if (i < n) { s[i] = 0; e[i] = 0; }
}

__global__ void bounds_kernel(const int* __restrict__ seg, int n,
                              int* __restrict__ s, int* __restrict__ e)
{
    int i = blockIdx.x * blockDim.x + threadIdx.x;
    if (i >= n) return;
    int id = seg[i];
    if (i == 0 || seg[i - 1] != id) s[id] = i;
    if (i == n - 1 || seg[i + 1] != id) e[id] = i + 1;
}

// ---------------------------------------------------------------------------
// One warp per user: fused[u] = concat(gcn_user_emb[users[u]], mean(item_emb))
// ---------------------------------------------------------------------------
__global__ void hist_kernel(const float* __restrict__ item_emb,
                            const int* __restrict__ item_idx,
                            const int* __restrict__ sa,
                            const int* __restrict__ ea,
                            const float* __restrict__ gue,
                            const int* __restrict__ users,
                            float* __restrict__ fused, int n_users)
{
    int w = (blockIdx.x * blockDim.x + threadIdx.x) >> 5;
    int lane = threadIdx.x & 31;
    if (w >= n_users) return;

    int uu = users[w];

    if (lane < 16) {
        float4 g = reinterpret_cast<const float4*>(gue + (size_t)uu * GCN)[lane];
        reinterpret_cast<float4*>(fused + (size_t)w * (GCN + TOW))[lane] = g;
    }

    int s = sa[uu], e = ea[uu];
    const float4* emb4 = reinterpret_cast<const float4*>(item_emb);

    float4 acc = make_float4(0.f, 0.f, 0.f, 0.f);
    int j = s;
    for (; j + 4 <= e; j += 4) {
        int i0 = item_idx[j], i1 = item_idx[j + 1], i2 = item_idx[j + 2], i3 = item_idx[j + 3];
        float4 v0 = emb4[(size_t)i0 * 32 + lane];
        float4 v1 = emb4[(size_t)i1 * 32 + lane];
        float4 v2 = emb4[(size_t)i2 * 32 + lane];
        float4 v3 = emb4[(size_t)i3 * 32 + lane];
        acc.x += (v0.x + v1.x) + (v2.x + v3.x);
        acc.y += (v0.y + v1.y) + (v2.y + v3.y);
        acc.z += (v0.z + v1.z) + (v2.z + v3.z);
        acc.w += (v0.w + v1.w) + (v2.w + v3.w);
    }
    for (; j < e; ++j) {
        int it = item_idx[j];
        float4 v = emb4[(size_t)it * 32 + lane];
        acc.x += v.x; acc.y += v.y; acc.z += v.z; acc.w += v.w;
    }
    float inv = 1.0f / fmaxf((float)(e - s), 1.0f);
    float4 m = make_float4(acc.x * inv, acc.y * inv, acc.z * inv, acc.w * inv);
    reinterpret_cast<float4*>(fused + (size_t)w * (GCN + TOW) + GCN)[lane] = m;
}

// ---------------------------------------------------------------------------
extern "C" void kernel_launch(void* const* d_in, const int* in_sizes, int n_in,
                              void* d_out, int out_size)
{
    const float* item_feat    = (const float*)d_in[0];
    const float* gcn_item_emb = (const float*)d_in[1];
    const float* gcn_user_emb = (const float*)d_in[2];
    const float* Wi1 = (const float*)d_in[3];
    const float* bi1 = (const float*)d_in[4];
    const float* Wi2 = (const float*)d_in[5];
    const float* bi2 = (const float*)d_in[6];
    const float* Wu1 = (const float*)d_in[7];
    const float* bu1 = (const float*)d_in[8];
    const float* Wu2 = (const float*)d_in[9];
    const float* bu2 = (const float*)d_in[10];
    const int* item_idx = (const int*)d_in[11];
    const int* seg_ids  = (const int*)d_in[12];
    const int* users    = (const int*)d_in[13];
    float* out = (float*)d_out;

    float *item_emb, *H, *fused;
    int *st, *en;
    cudaGetSymbolAddress((void**)&item_emb, g_item_emb);
    cudaGetSymbolAddress((void**)&H, g_H);
    cudaGetSymbolAddress((void**)&fused, g_fused);
    cudaGetSymbolAddress((void**)&st, g_start);
    cudaGetSymbolAddress((void**)&en, g_end);

    // smem per instantiation: Ws[N*K4] + Xs[TR*K4] (+ Sr[8*R] for L2N)
    constexpr int K4_i1 = PadK<66>::value;    // 68
    constexpr int K4_l2 = PadK<256>::value;   // 260
    constexpr int K4_u1 = PadK<192>::value;   // 196
    const int smem_i1 = (256 * K4_i1 + 32 * K4_i1) * 4;                 // ~78 KB
    const int smem_l2 = (128 * K4_l2 + 64 * K4_l2 + 8 * 16) * 4;        // ~196 KB
    const int smem_u1 = (256 * K4_u1 + 32 * K4_u1) * 4;                 // ~226 KB

    cudaFuncSetAttribute((const void*)gemm_kernel<66, 256, true, false>,
                         cudaFuncAttributeMaxDynamicSharedMemorySize, smem_i1);
    cudaFuncSetAttribute((const void*)gemm_kernel<256, 128, false, true>,
                         cudaFuncAttributeMaxDynamicSharedMemorySize, smem_l2);
    cudaFuncSetAttribute((const void*)gemm_kernel<192, 256, true, false>,
                         cudaFuncAttributeMaxDynamicSharedMemorySize, smem_u1);

    const int GRID = 152;   // persistent, 1 CTA per SM

    // 1) item L1: H = relu(concat(item_feat, gcn_item_emb) @ Wi1 + bi1)
    gemm_kernel<66, 256, true, false><<<GRID, 256, smem_i1>>>(
        item_feat, 2, gcn_item_emb, Wi1, bi1, H, N_ITEMS);

    // 2) item L2 + L2 norm -> item_emb
    gemm_kernel<256, 128, false, true><<<GRID, 256, smem_l2>>>(
        H, 256, H, Wi2, bi2, item_emb, N_ITEMS);

    // 3) segment boundaries
    bounds_init_kernel<<<(N_USERS + 255) / 256, 256>>>(st, en, N_USERS);
    bounds_kernel<<<(N_INTER + 255) / 256, 256>>>(seg_ids, N_INTER, st, en);

    // 4) ragged gather + mean -> fused
    hist_kernel<<<(N_USERS * 32 + 255) / 256, 256>>>(
        item_emb, item_idx, st, en, gcn_user_emb, users, fused, N_USERS);

    // 5) user L1
    gemm_kernel<192, 256, true, false><<<GRID, 256, smem_u1>>>(
        fused, 192, fused, Wu1, bu1, H, N_USERS);

    // 6) user L2 + L2 norm -> output
    gemm_kernel<256, 128, false, true><<<GRID, 256, smem_l2>>>(
        H, 256, H, Wu2, bu2, out, N_USERS);
}

// round 5
// speedup vs baseline: 1.8752x; 1.8752x over previous
#include <cuda_runtime.h>
#include <math.h>

#define N_ITEMS 200000
#define N_USERS 100000
#define N_INTER 2000000
#define GCN 64
#define HID 256
#define TOW 128

typedef unsigned long long u64;

// packed dual-FMA: (d.lo,d.hi) += (a.lo*b.lo, a.hi*b.hi)
#define FMA2(d, a, b) \
    asm("fma.rn.f32x2 %0, %1, %2, %0;" : "+l"(d) : "l"(a), "l"(b))

#define UNPACK2(lo, hi, p) \
    asm("mov.b64 {%0, %1}, %2;" : "=f"(lo), "=f"(hi) : "l"(p))

// ---------------- scratch (static device globals; no runtime alloc) ----------
__device__ float g_item_emb[(size_t)N_ITEMS * TOW];      // 102.4 MB
__device__ float g_H[(size_t)N_ITEMS * HID];             // 204.8 MB (reused by user tower)
__device__ float g_fused[(size_t)N_USERS * (GCN + TOW)]; // 76.8 MB
__device__ int   g_start[N_USERS];
__device__ int   g_end[N_USERS];

// padded K stride: ends up ≡4 (mod 32) for all our K (68/196/260) ->
// stride-K4 LDS.128 / STS across lanes is bank-conflict-free.
template <int K> struct PadK {
    static constexpr int a = (K + 3) & ~3;
    static constexpr int value = (a % 8 == 4) ? a : a + 4;
};

// ---------------------------------------------------------------------------
// Fused layer: Y = post( X @ W + b )
//  - LANES threads span N (C = N/LANES = 4 cols per thread)
//  - 256/LANES row-groups x R=8 rows per thread
//  - W transposed into SMEM [N][K4] once per CTA (coalesced reads)
//  - f32x2 FMA packed along k; per 4-k group: C w-loads + R x-broadcasts
//  - RELU: bias+relu+store.  L2N (N==128, LANES==32): warp-local row L2 norm.
//  - CONCAT (layer 1): X = concat(X1[:k1], X2[:K-k1]) scalar staging;
//    otherwise float4 staging from X1.
// ---------------------------------------------------------------------------
template <int K, int N, int LANES, bool RELU, bool L2N, bool CONCAT>
__global__ void __launch_bounds__(256, 1)
gemm_kernel(const float* __restrict__ X1, int k1,
            const float* __restrict__ X2,
            const float* __restrict__ W,
            const float* __restrict__ bias,
            float* __restrict__ Y, int M)
{
    constexpr int K4 = PadK<K>::value;
    constexpr int C  = N / LANES;          // 4
    constexpr int R  = 8;                  // rows per thread
    constexpr int G  = 256 / LANES;        // row-groups
    constexpr int TR = G * R;              // tile rows (64 for LANES=32, 32 for 64)
    constexpr int NG = K4 / 4;             // 4-k groups

    static_assert(C == 4, "layout assumes 4 cols/thread");
    static_assert(!L2N || (N == 128 && LANES == 32), "L2N path: N=128, warp-local");

    extern __shared__ float sm[];
    float* Ws = sm;                        // [N][K4] transposed weights
    float* Xs = sm + (size_t)N * K4;       // [TR][K4]

    const int tid = threadIdx.x;
    const int ty  = tid / LANES;           // row-group
    const int tx  = tid % LANES;           // col lane

    // ---- stage transposed weights (coalesced LDG, strided STS) ----
    for (int i = tid; i < K * N; i += 256) {
        int k = i / N, n = i - k * N;
        Ws[n * K4 + k] = W[i];
    }
    for (int i = tid; i < N * (K4 - K); i += 256) {
        int n = i / (K4 - K), k = K + (i - n * (K4 - K));
        Ws[n * K4 + k] = 0.f;
    }

    float breg[C];
#pragma unroll
    for (int j = 0; j < C; ++j) breg[j] = bias[tx + LANES * j];

    const ulonglong2* wp[C];
#pragma unroll
    for (int j = 0; j < C; ++j)
        wp[j] = reinterpret_cast<const ulonglong2*>(Ws + (size_t)(tx + LANES * j) * K4);
    const ulonglong2* xp[R];
#pragma unroll
    for (int i = 0; i < R; ++i)
        xp[i] = reinterpret_cast<const ulonglong2*>(Xs + (size_t)(ty + G * i) * K4);

    const int ntiles = (M + TR - 1) / TR;
    for (int tile = blockIdx.x; tile < ntiles; tile += gridDim.x) {
        const int row0 = tile * TR;
        __syncthreads();   // protect Xs from previous iteration (and W load, 1st)

        if (CONCAT) {
            for (int i = tid; i < TR * K4; i += 256) {
                int r = i / K4, c = i - r * K4;
                int gr = row0 + r;
                float v = 0.f;
                if (gr < M && c < K)
                    v = (c < k1) ? X1[(size_t)gr * k1 + c]
                                 : X2[(size_t)gr * (K - k1) + (c - k1)];
                Xs[i] = v;
            }
        } else {
            constexpr int KV = K / 4;
            const float4* X4 = reinterpret_cast<const float4*>(X1);
            for (int i = tid; i < TR * KV; i += 256) {
                int r = i / KV, c = i - r * KV;
                int gr = row0 + r;
                float4 v = make_float4(0.f, 0.f, 0.f, 0.f);
                if (gr < M) v = X4[(size_t)gr * KV + c];
                *reinterpret_cast<float4*>(Xs + r * K4 + 4 * c) = v;
            }
            if (tid < TR)
                *reinterpret_cast<float4*>(Xs + tid * K4 + K) =
                    make_float4(0.f, 0.f, 0.f, 0.f);
        }
        __syncthreads();

        u64 acc[R][C];
#pragma unroll
        for (int i = 0; i < R; ++i)
#pragma unroll
            for (int j = 0; j < C; ++j) acc[i][j] = 0ull;

#pragma unroll 2
        for (int g = 0; g < NG; ++g) {
            ulonglong2 w[C];
#pragma unroll
            for (int j = 0; j < C; ++j) w[j] = wp[j][g];
#pragma unroll
            for (int i = 0; i < R; ++i) {
                ulonglong2 a = xp[i][g];   // warp-broadcast
#pragma unroll
                for (int j = 0; j < C; ++j) {
                    FMA2(acc[i][j], a.x, w[j].x);
                    FMA2(acc[i][j], a.y, w[j].y);
                }
            }
        }

        float val[R][C];
#pragma unroll
        for (int i = 0; i < R; ++i)
#pragma unroll
            for (int j = 0; j < C; ++j) {
                float lo, hi;
                UNPACK2(lo, hi, acc[i][j]);
                val[i][j] = lo + hi + breg[j];
            }

        if (RELU) {
#pragma unroll
            for (int i = 0; i < R; ++i) {
                int gr = row0 + ty + G * i;
                if (gr < M) {
#pragma unroll
                    for (int j = 0; j < C; ++j)
                        Y[(size_t)gr * N + tx + LANES * j] = fmaxf(val[i][j], 0.f);
                }
            }
        } else {   // L2N: each row fully inside one warp -> shfl reduce only
#pragma unroll
            for (int i = 0; i < R; ++i) {
                float s = val[i][0] * val[i][0] + val[i][1] * val[i][1]
                        + val[i][2] * val[i][2] + val[i][3] * val[i][3];
#pragma unroll
                for (int o = 16; o > 0; o >>= 1)
                    s += __shfl_xor_sync(0xffffffffu, s, o);
                float scale = 1.0f / fmaxf(sqrtf(s), 1e-12f);
                int gr = row0 + ty + G * i;
                if (gr < M) {
#pragma unroll
                    for (int j = 0; j < C; ++j)
                        Y[(size_t)gr * 128 + tx + 32 * j] = val[i][j] * scale;
                }
            }
        }
    }
}

// ---------------------------------------------------------------------------
// Segment boundaries from sorted seg_ids (users with no interactions -> [0,0))
// ---------------------------------------------------------------------------
__global__ void bounds_init_kernel(int* __restrict__ s, int* __restrict__ e, int n)
{
    int i = blockIdx.x * blockDim.x + threadIdx.x;
    if (i < n) { s[i] = 0; e[i] = 0; }
}

__global__ void bounds_kernel(const int* __restrict__ seg, int n,
                              int* __restrict__ s, int* __restrict__ e)
{
    int i = blockIdx.x * blockDim.x + threadIdx.x;
    if (i >= n) return;
    int id = seg[i];
    if (i == 0 || seg[i - 1] != id) s[id] = i;
    if (i == n - 1 || seg[i + 1] != id) e[id] = i + 1;
}

// ---------------------------------------------------------------------------
// One warp per user: fused[u] = concat(gcn_user_emb[users[u]], mean(item_emb))
// ---------------------------------------------------------------------------
__global__ void hist_kernel(const float* __restrict__ item_emb,
                            const int* __restrict__ item_idx,
                            const int* __restrict__ sa,
                            const int* __restrict__ ea,
                            const float* __restrict__ gue,
                            const int* __restrict__ users,
                            float* __restrict__ fused, int n_users)
{
    int w = (blockIdx.x * blockDim.x + threadIdx.x) >> 5;
    int lane = threadIdx.x & 31;
    if (w >= n_users) return;

    int uu = users[w];

    if (lane < 16) {
        float4 g = reinterpret_cast<const float4*>(gue + (size_t)uu * GCN)[lane];
        reinterpret_cast<float4*>(fused + (size_t)w * (GCN + TOW))[lane] = g;
    }

    int s = sa[uu], e = ea[uu];
    const float4* emb4 = reinterpret_cast<const float4*>(item_emb);

    float4 acc = make_float4(0.f, 0.f, 0.f, 0.f);
    int j = s;
    for (; j + 4 <= e; j += 4) {
        int i0 = item_idx[j], i1 = item_idx[j + 1], i2 = item_idx[j + 2], i3 = item_idx[j + 3];
        float4 v0 = emb4[(size_t)i0 * 32 + lane];
        float4 v1 = emb4[(size_t)i1 * 32 + lane];
        float4 v2 = emb4[(size_t)i2 * 32 + lane];
        float4 v3 = emb4[(size_t)i3 * 32 + lane];
        acc.x += (v0.x + v1.x) + (v2.x + v3.x);
        acc.y += (v0.y + v1.y) + (v2.y + v3.y);
        acc.z += (v0.z + v1.z) + (v2.z + v3.z);
        acc.w += (v0.w + v1.w) + (v2.w + v3.w);
    }
    for (; j < e; ++j) {
        int it = item_idx[j];
        float4 v = emb4[(size_t)it * 32 + lane];
        acc.x += v.x; acc.y += v.y; acc.z += v.z; acc.w += v.w;
    }
    float inv = 1.0f / fmaxf((float)(e - s), 1.0f);
    float4 m = make_float4(acc.x * inv, acc.y * inv, acc.z * inv, acc.w * inv);
    reinterpret_cast<float4*>(fused + (size_t)w * (GCN + TOW) + GCN)[lane] = m;
}

// ---------------------------------------------------------------------------
extern "C" void kernel_launch(void* const* d_in, const int* in_sizes, int n_in,
                              void* d_out, int out_size)
{
    const float* item_feat    = (const float*)d_in[0];
    const float* gcn_item_emb = (const float*)d_in[1];
    const float* gcn_user_emb = (const float*)d_in[2];
    const float* Wi1 = (const float*)d_in[3];
    const float* bi1 = (const float*)d_in[4];
    const float* Wi2 = (const float*)d_in[5];
    const float* bi2 = (const float*)d_in[6];
    const float* Wu1 = (const float*)d_in[7];
    const float* bu1 = (const float*)d_in[8];
    const float* Wu2 = (const float*)d_in[9];
    const float* bu2 = (const float*)d_in[10];
    const int* item_idx = (const int*)d_in[11];
    const int* seg_ids  = (const int*)d_in[12];
    const int* users    = (const int*)d_in[13];
    float* out = (float*)d_out;

    float *item_emb, *H, *fused;
    int *st, *en;
    cudaGetSymbolAddress((void**)&item_emb, g_item_emb);
    cudaGetSymbolAddress((void**)&H, g_H);
    cudaGetSymbolAddress((void**)&fused, g_fused);
    cudaGetSymbolAddress((void**)&st, g_start);
    cudaGetSymbolAddress((void**)&en, g_end);

    constexpr int K4_i1 = PadK<66>::value;    // 68
    constexpr int K4_l2 = PadK<256>::value;   // 260
    constexpr int K4_u1 = PadK<192>::value;   // 196
    // Ws[N*K4] + Xs[TR*K4]
    const int smem_i1 = (256 * K4_i1 + 32 * K4_i1) * 4;   // 78,336
    const int smem_l2 = (128 * K4_l2 + 64 * K4_l2) * 4;   // 199,680
    const int smem_u1 = (256 * K4_u1 + 32 * K4_u1) * 4;   // 225,792

    cudaFuncSetAttribute((const void*)gemm_kernel<66, 256, 64, true, false, true>,
                         cudaFuncAttributeMaxDynamicSharedMemorySize, smem_i1);
    cudaFuncSetAttribute((const void*)gemm_kernel<256, 128, 32, false, true, false>,
                         cudaFuncAttributeMaxDynamicSharedMemorySize, smem_l2);
    cudaFuncSetAttribute((const void*)gemm_kernel<192, 256, 64, true, false, false>,
                         cudaFuncAttributeMaxDynamicSharedMemorySize, smem_u1);

    const int GRID = 152;   // persistent, 1 CTA per SM

    // 1) item L1: H = relu(concat(item_feat, gcn_item_emb) @ Wi1 + bi1)
    gemm_kernel<66, 256, 64, true, false, true><<<GRID, 256, smem_i1>>>(
        item_feat, 2, gcn_item_emb, Wi1, bi1, H, N_ITEMS);

    // 2) item L2 + L2 norm -> item_emb
    gemm_kernel<256, 128, 32, false, true, false><<<GRID, 256, smem_l2>>>(
        H, 256, H, Wi2, bi2, item_emb, N_ITEMS);

    // 3) segment boundaries
    bounds_init_kernel<<<(N_USERS + 255) / 256, 256>>>(st, en, N_USERS);
    bounds_kernel<<<(N_INTER + 255) / 256, 256>>>(seg_ids, N_INTER, st, en);

    // 4) ragged gather + mean -> fused
    hist_kernel<<<(N_USERS * 32 + 255) / 256, 256>>>(
        item_emb, item_idx, st, en, gcn_user_emb, users, fused, N_USERS);

    // 5) user L1
    gemm_kernel<192, 256, 64, true, false, false><<<GRID, 256, smem_u1>>>(
        fused, 192, fused, Wu1, bu1, H, N_USERS);

    // 6) user L2 + L2 norm -> output
    gemm_kernel<256, 128, 32, false, true, false><<<GRID, 256, smem_l2>>>(
        H, 256, H, Wu2, bu2, out, N_USERS);
}

// round 7
// speedup vs baseline: 1.9532x; 1.0416x over previous
#include <cuda_runtime.h>
#include <math.h>

#define N_ITEMS 200000
#define N_USERS 100000
#define N_INTER 2000000
#define GCN 64
#define HID 256
#define TOW 128

typedef unsigned long long u64;

// packed dual-FMA: (d.lo,d.hi) += (a.lo*b.lo, a.hi*b.hi)
#define FMA2(d, a, b) \
    asm("fma.rn.f32x2 %0, %1, %2, %0;" : "+l"(d) : "l"(a), "l"(b))

#define UNPACK2(lo, hi, p) \
    asm("mov.b64 {%0, %1}, %2;" : "=f"(lo), "=f"(hi) : "l"(p))

// ---------------- scratch (static device globals; no runtime alloc) ----------
__device__ float g_item_emb[(size_t)N_ITEMS * TOW];      // 102.4 MB
__device__ float g_H[(size_t)N_ITEMS * HID];             // 204.8 MB
__device__ float g_fused[(size_t)N_USERS * (GCN + TOW)]; // 76.8 MB
__device__ int   g_start[N_USERS];
__device__ int   g_end[N_USERS];

// padded stride: multiple of 4 words AND ≡4 (mod 8) -> stride-K4 LDS.128 / STS
// across lanes is bank-conflict-free (since K4 ≡ 4 mod 32 for all our K).
template <int K> struct PadK {
    static constexpr int a = (K + 3) & ~3;
    static constexpr int value = (a % 8 == 4) ? a : a + 4;
};

// ---------------------------------------------------------------------------
// Fused layer: Y = post( X @ W + b )
//  - LANES lanes span N (C=4 cols per thread), G=256/LANES row-groups,
//    R=16 rows per thread -> TR = G*16 tile rows
//  - W transposed in SMEM [N][K4w] whole; X staged in SPLIT K-chunks
//    (Xs = [TR][KC4]) so smem fits; zero-padded chunk tails are harmless
//  - f32x2 FMA packed along k; per 4-k group: 4 distinct w-loads (4 cyc each)
//    + 16 x-broadcasts (1 cyc)  vs  64 FMA2 -> crossbar/FMA balanced
//  - RELU: bias+relu+store.  L2N (N==128, LANES==32): warp-local row L2 norm.
// ---------------------------------------------------------------------------
template <int K, int N, int LANES, int SPLIT, bool RELU, bool L2N, bool CONCAT>
__global__ void __launch_bounds__(256, 1)
gemm_kernel(const float* __restrict__ X1, int k1,
            const float* __restrict__ X2,
            const float* __restrict__ W,
            const float* __restrict__ bias,
            float* __restrict__ Y, int M)
{
    constexpr int KC  = K / SPLIT;
    constexpr int KC4 = PadK<KC>::value;
    constexpr int K4w = PadK<K>::value;
    constexpr int C   = 4;
    constexpr int R   = 16;
    constexpr int G   = 256 / LANES;
    constexpr int TR  = G * R;
    constexpr int NG  = KC4 / 4;

    static_assert(N == LANES * C, "4 cols per thread");
    static_assert(!L2N || (N == 128 && LANES == 32), "L2N: warp-local rows");
    static_assert(!CONCAT || SPLIT == 1, "concat layer is single-chunk");

    extern __shared__ float sm[];
    float* Ws = sm;                          // [N][K4w]
    float* Xs = sm + (size_t)N * K4w;        // [TR][KC4]

    const int tid = threadIdx.x;
    const int ty  = tid / LANES;
    const int tx  = tid % LANES;

    // ---- stage transposed weights (coalesced LDG, strided STS) ----
    for (int i = tid; i < K * N; i += 256) {
        int k = i / N, n = i - k * N;
        Ws[n * K4w + k] = W[i];
    }
    for (int i = tid; i < N * (K4w - K); i += 256) {
        int n = i / (K4w - K), k = K + (i - n * (K4w - K));
        Ws[n * K4w + k] = 0.f;
    }

    float breg[C];
#pragma unroll
    for (int j = 0; j < C; ++j) breg[j] = bias[tx + LANES * j];

    // single base pointers; all other offsets are compile-time immediates
    const ulonglong2* wb = reinterpret_cast<const ulonglong2*>(Ws + (size_t)tx * K4w);
    const ulonglong2* xb = reinterpret_cast<const ulonglong2*>(Xs + (size_t)ty * KC4);
    constexpr int WSTEP = LANES * K4w / 4;   // ulonglong2 stride between col-groups
    constexpr int XSTEP = G * KC4 / 4;       // ulonglong2 stride between row-groups

    const int ntiles = (M + TR - 1) / TR;
    for (int tile = blockIdx.x; tile < ntiles; tile += gridDim.x) {
        const int row0 = tile * TR;

        u64 acc[R][C];
#pragma unroll
        for (int i = 0; i < R; ++i)
#pragma unroll
            for (int j = 0; j < C; ++j) acc[i][j] = 0ull;

#pragma unroll
        for (int cch = 0; cch < SPLIT; ++cch) {
            __syncthreads();   // prior readers of Xs done (and W stage, 1st iter)

            if (CONCAT) {
                // row units: q==16 -> item_feat cols 0,1 + pad cols; else gcn float4
                const float4* G4 = reinterpret_cast<const float4*>(X2);
                for (int u = tid; u < TR * 17; u += 256) {
                    int r = u / 17, q = u - r * 17;
                    int gr = row0 + r;
                    if (q == 16) {
                        float a0 = 0.f, a1 = 0.f;
                        if (gr < M) { a0 = X1[gr * 2]; a1 = X1[gr * 2 + 1]; }
                        Xs[r * KC4 + 0] = a0;
                        Xs[r * KC4 + 1] = a1;
                        Xs[r * KC4 + 66] = 0.f;
                        Xs[r * KC4 + 67] = 0.f;
                    } else {
                        float4 v = make_float4(0.f, 0.f, 0.f, 0.f);
                        if (gr < M) v = G4[(size_t)gr * 16 + q];
                        int c0 = 2 + 4 * q;
                        Xs[r * KC4 + c0]     = v.x;
                        Xs[r * KC4 + c0 + 1] = v.y;
                        Xs[r * KC4 + c0 + 2] = v.z;
                        Xs[r * KC4 + c0 + 3] = v.w;
                    }
                }
            } else {
                constexpr int KV = KC / 4;          // float4 per row per chunk
                const float4* X4 = reinterpret_cast<const float4*>(X1);
                for (int i = tid; i < TR * KV; i += 256) {
                    int r = i / KV, c = i - r * KV;
                    int gr = row0 + r;
                    float4 v = make_float4(0.f, 0.f, 0.f, 0.f);
                    if (gr < M) v = X4[(size_t)gr * (K / 4) + cch * KV + c];
                    *reinterpret_cast<float4*>(Xs + r * KC4 + 4 * c) = v;
                }
                if (tid < TR)   // zero the 4-word chunk pad
                    *reinterpret_cast<float4*>(Xs + tid * KC4 + KC) =
                        make_float4(0.f, 0.f, 0.f, 0.f);
            }
            __syncthreads();

            const int goff = cch * (KC / 4);
#pragma unroll 1
            for (int g = 0; g < NG; ++g) {
                ulonglong2 w[C];
#pragma unroll
                for (int j = 0; j < C; ++j) w[j] = wb[goff + g + j * WSTEP];
#pragma unroll
                for (int i = 0; i < R; ++i) {
                    ulonglong2 a = xb[g + i * XSTEP];   // warp-broadcast
#pragma unroll
                    for (int j = 0; j < C; ++j) {
                        FMA2(acc[i][j], a.x, w[j].x);
                        FMA2(acc[i][j], a.y, w[j].y);
                    }
                }
            }
        }

        // ---- epilogue (registers + shfl only; no smem) ----
        float val[R][C];
#pragma unroll
        for (int i = 0; i < R; ++i)
#pragma unroll
            for (int j = 0; j < C; ++j) {
                float lo, hi;
                UNPACK2(lo, hi, acc[i][j]);
                val[i][j] = lo + hi + breg[j];
            }

        if (RELU) {
#pragma unroll
            for (int i = 0; i < R; ++i) {
                int gr = row0 + ty + G * i;
                if (gr < M) {
#pragma unroll
                    for (int j = 0; j < C; ++j)
                        Y[(size_t)gr * N + tx + LANES * j] = fmaxf(val[i][j], 0.f);
                }
            }
        } else {   // L2N: each row lives in one warp
#pragma unroll
            for (int i = 0; i < R; ++i) {
                float s = val[i][0] * val[i][0] + val[i][1] * val[i][1]
                        + val[i][2] * val[i][2] + val[i][3] * val[i][3];
#pragma unroll
                for (int o = 16; o > 0; o >>= 1)
                    s += __shfl_xor_sync(0xffffffffu, s, o);
                float scale = 1.0f / fmaxf(sqrtf(s), 1e-12f);
                int gr = row0 + ty + G * i;
                if (gr < M) {
#pragma unroll
                    for (int j = 0; j < C; ++j)
                        Y[(size_t)gr * 128 + tx + 32 * j] = val[i][j] * scale;
                }
            }
        }
    }
}

// ---------------------------------------------------------------------------
// Segment boundaries from sorted seg_ids (users with no interactions -> [0,0))
// ---------------------------------------------------------------------------
__global__ void bounds_init_kernel(int* __restrict__ s, int* __restrict__ e, int n)
{
    int i = blockIdx.x * blockDim.x + threadIdx.x;
    if (i < n) { s[i] = 0; e[i] = 0; }
}

__global__ void bounds_kernel(const int* __restrict__ seg, int n,
                              int* __restrict__ s, int* __restrict__ e)
{
    int i = blockIdx.x * blockDim.x + threadIdx.x;
    if (i >= n) return;
    int id = seg[i];
    if (i == 0 || seg[i - 1] != id) s[id] = i;
    if (i == n - 1 || seg[i + 1] != id) e[id] = i + 1;
}

// ---------------------------------------------------------------------------
// One warp per user: fused[u] = concat(gcn_user_emb[users[u]], mean(item_emb))
// ---------------------------------------------------------------------------
__global__ void hist_kernel(const float* __restrict__ item_emb,
                            const int* __restrict__ item_idx,
                            const int* __restrict__ sa,
                            const int* __restrict__ ea,
                            const float* __restrict__ gue,
                            const int* __restrict__ users,
                            float* __restrict__ fused, int n_users)
{
    int w = (blockIdx.x * blockDim.x + threadIdx.x) >> 5;
    int lane = threadIdx.x & 31;
    if (w >= n_users) return;

    int uu = users[w];

    if (lane < 16) {
        float4 g = reinterpret_cast<const float4*>(gue + (size_t)uu * GCN)[lane];
        reinterpret_cast<float4*>(fused + (size_t)w * (GCN + TOW))[lane] = g;
    }

    int s = sa[uu], e = ea[uu];
    const float4* emb4 = reinterpret_cast<const float4*>(item_emb);

    float4 acc = make_float4(0.f, 0.f, 0.f, 0.f);
    int j = s;
    for (; j + 4 <= e; j += 4) {
        int i0 = item_idx[j], i1 = item_idx[j + 1], i2 = item_idx[j + 2], i3 = item_idx[j + 3];
        float4 v0 = emb4[(size_t)i0 * 32 + lane];
        float4 v1 = emb4[(size_t)i1 * 32 + lane];
        float4 v2 = emb4[(size_t)i2 * 32 + lane];
        float4 v3 = emb4[(size_t)i3 * 32 + lane];
        acc.x += (v0.x + v1.x) + (v2.x + v3.x);
        acc.y += (v0.y + v1.y) + (v2.y + v3.y);
        acc.z += (v0.z + v1.z) + (v2.z + v3.z);
        acc.w += (v0.w + v1.w) + (v2.w + v3.w);
    }
    for (; j < e; ++j) {
        int it = item_idx[j];
        float4 v = emb4[(size_t)it * 32 + lane];
        acc.x += v.x; acc.y += v.y; acc.z += v.z; acc.w += v.w;
    }
    float inv = 1.0f / fmaxf((float)(e - s), 1.0f);
    float4 m = make_float4(acc.x * inv, acc.y * inv, acc.z * inv, acc.w * inv);
    reinterpret_cast<float4*>(fused + (size_t)w * (GCN + TOW) + GCN)[lane] = m;
}

// ---------------------------------------------------------------------------
extern "C" void kernel_launch(void* const* d_in, const int* in_sizes, int n_in,
                              void* d_out, int out_size)
{
    const float* item_feat    = (const float*)d_in[0];
    const float* gcn_item_emb = (const float*)d_in[1];
    const float* gcn_user_emb = (const float*)d_in[2];
    const float* Wi1 = (const float*)d_in[3];
    const float* bi1 = (const float*)d_in[4];
    const float* Wi2 = (const float*)d_in[5];
    const float* bi2 = (const float*)d_in[6];
    const float* Wu1 = (const float*)d_in[7];
    const float* bu1 = (const float*)d_in[8];
    const float* Wu2 = (const float*)d_in[9];
    const float* bu2 = (const float*)d_in[10];
    const int* item_idx = (const int*)d_in[11];
    const int* seg_ids  = (const int*)d_in[12];
    const int* users    = (const int*)d_in[13];
    float* out = (float*)d_out;

    float *item_emb, *H, *fused;
    int *st, *en;
    cudaGetSymbolAddress((void**)&item_emb, g_item_emb);
    cudaGetSymbolAddress((void**)&H, g_H);
    cudaGetSymbolAddress((void**)&fused, g_fused);
    cudaGetSymbolAddress((void**)&st, g_start);
    cudaGetSymbolAddress((void**)&en, g_end);

    // instantiations:
    //  i1: K=66  N=256 LANES=64 SPLIT=1 CONCAT  TR=64
    //  l2: K=256 N=128 LANES=32 SPLIT=2 L2N     TR=128
    //  u1: K=192 N=256 LANES=64 SPLIT=2 RELU    TR=64
    const int smem_i1 = (256 * PadK<66>::value  + 64  * PadK<66>::value)  * 4; //  87,040
    const int smem_l2 = (128 * PadK<256>::value + 128 * PadK<128>::value) * 4; // 200,704
    const int smem_u1 = (256 * PadK<192>::value + 64  * PadK<96>::value)  * 4; // 226,304

    cudaFuncSetAttribute((const void*)gemm_kernel<66, 256, 64, 1, true, false, true>,
                         cudaFuncAttributeMaxDynamicSharedMemorySize, smem_i1);
    cudaFuncSetAttribute((const void*)gemm_kernel<256, 128, 32, 2, false, true, false>,
                         cudaFuncAttributeMaxDynamicSharedMemorySize, smem_l2);
    cudaFuncSetAttribute((const void*)gemm_kernel<192, 256, 64, 2, true, false, false>,
                         cudaFuncAttributeMaxDynamicSharedMemorySize, smem_u1);

    const int GRID = 152;   // persistent, 1 CTA per SM

    // 1) item L1: H = relu(concat(item_feat, gcn_item_emb) @ Wi1 + bi1)
    gemm_kernel<66, 256, 64, 1, true, false, true><<<GRID, 256, smem_i1>>>(
        item_feat, 2, gcn_item_emb, Wi1, bi1, H, N_ITEMS);

    // 2) item L2 + L2 norm -> item_emb
    gemm_kernel<256, 128, 32, 2, false, true, false><<<GRID, 256, smem_l2>>>(
        H, 256, H, Wi2, bi2, item_emb, N_ITEMS);

    // 3) segment boundaries
    bounds_init_kernel<<<(N_USERS + 255) / 256, 256>>>(st, en, N_USERS);
    bounds_kernel<<<(N_INTER + 255) / 256, 256>>>(seg_ids, N_INTER, st, en);

    // 4) ragged gather + mean -> fused
    hist_kernel<<<(N_USERS * 32 + 255) / 256, 256>>>(
        item_emb, item_idx, st, en, gcn_user_emb, users, fused, N_USERS);

    // 5) user L1
    gemm_kernel<192, 256, 64, 2, true, false, false><<<GRID, 256, smem_u1>>>(
        fused, 192, fused, Wu1, bu1, H, N_USERS);

    // 6) user L2 + L2 norm -> output
    gemm_kernel<256, 128, 32, 2, false, true, false><<<GRID, 256, smem_l2>>>(
        H, 256, H, Wu2, bu2, out, N_USERS);
}

// round 8
// speedup vs baseline: 2.2197x; 1.1364x over previous
#include <cuda_runtime.h>
#include <math.h>
#include <stdint.h>

#define N_ITEMS 200000
#define N_USERS 100000
#define N_INTER 2000000
#define GCN 64
#define HID 256
#define TOW 128

typedef unsigned long long u64;

// packed dual-FMA: (d.lo,d.hi) += (a.lo*b.lo, a.hi*b.hi)
#define FMA2(d, a, b) \
    asm("fma.rn.f32x2 %0, %1, %2, %0;" : "+l"(d) : "l"(a), "l"(b))

#define UNPACK2(lo, hi, p) \
    asm("mov.b64 {%0, %1}, %2;" : "=f"(lo), "=f"(hi) : "l"(p))

__device__ __forceinline__ uint32_t smem_u32(const void* p) {
    uint32_t a;
    asm("{ .reg .u64 t; cvta.to.shared.u64 t, %1; cvt.u32.u64 %0, t; }"
        : "=r"(a) : "l"(p));
    return a;
}

// cp.async 16B with runtime src-size (0 -> zero-fill)
#define CP_ASYNC16(dst_u32, src_ptr, nbytes) \
    asm volatile("cp.async.cg.shared.global [%0], [%1], 16, %2;" \
                 :: "r"(dst_u32), "l"(src_ptr), "r"(nbytes))
#define CP_COMMIT() asm volatile("cp.async.commit_group;" ::: "memory")
template <int NPend>
__device__ __forceinline__ void cp_wait() {
    asm volatile("cp.async.wait_group %0;" :: "n"(NPend) : "memory");
}

// ---------------- scratch (static device globals; no runtime alloc) ----------
__device__ float g_item_emb[(size_t)N_ITEMS * TOW];      // 102.4 MB
__device__ float g_H[(size_t)N_ITEMS * HID];             // 204.8 MB
__device__ float g_fused[(size_t)N_USERS * (GCN + TOW)]; // 76.8 MB
__device__ int   g_start[N_USERS];
__device__ int   g_end[N_USERS];

// padded stride: multiple of 4 words AND ≡4 (mod 8) -> ≡4 (mod 32) for our K;
// stride-K4 LDS.128 across lanes is bank-conflict-free.
template <int K> struct PadK {
    static constexpr int a = (K + 3) & ~3;
    static constexpr int value = (a % 8 == 4) ? a : a + 4;
};

// ---------------------------------------------------------------------------
// Fused layer: Y = post( X @ W + b )   [512 threads, persistent CTAs]
//  - LANES lanes span N (C=4 cols/thread), G=512/LANES row-groups, R=8 rows
//  - W transposed whole in SMEM [N][K4w] (zero-padded tail)
//  - X staged in SPLIT K-chunks, DOUBLE-BUFFERED via cp.async (overlap with
//    compute); chunk pad words zeroed once (bufs only ever rewritten in the
//    first KC words per row)
//  - RELU: bias+relu+store.  L2N (N==128, LANES==32): warp-local row L2 norm.
// ---------------------------------------------------------------------------
template <int K, int N, int LANES, int SPLIT, bool RELU, bool L2N, bool CONCAT>
__global__ void __launch_bounds__(512, 1)
gemm_kernel(const float* __restrict__ X1, int k1,
            const float* __restrict__ X2,
            const float* __restrict__ W,
            const float* __restrict__ bias,
            float* __restrict__ Y, int M)
{
    constexpr int THREADS = 512;
    constexpr int KC  = K / SPLIT;
    constexpr int KC4 = PadK<KC>::value;
    constexpr int K4w = PadK<K>::value;
    constexpr int C   = 4;
    constexpr int R   = 8;
    constexpr int G   = THREADS / LANES;
    constexpr int TR  = G * R;
    constexpr int NG  = KC4 / 4;
    constexpr int NBUF = (SPLIT > 1) ? 2 : 1;

    static_assert(N == LANES * C, "4 cols per thread");
    static_assert(K % SPLIT == 0, "even K split");
    static_assert(!L2N || (N == 128 && LANES == 32), "L2N: warp-local rows");
    static_assert(!CONCAT || SPLIT == 1, "concat layer is single-chunk");

    extern __shared__ float sm[];
    float* Ws = sm;                          // [N][K4w]
    float* Xb[NBUF];
    Xb[0] = sm + (size_t)N * K4w;
    if (NBUF == 2) Xb[1] = Xb[0] + (size_t)TR * KC4;

    const int tid = threadIdx.x;
    const int ty  = tid / LANES;
    const int tx  = tid % LANES;

    // ---- stage transposed weights (coalesced LDG, strided STS) ----
    for (int i = tid; i < K * N; i += THREADS) {
        int k = i / N, n = i - k * N;
        Ws[n * K4w + k] = W[i];
    }
    for (int i = tid; i < N * (K4w - K); i += THREADS) {
        int n = i / (K4w - K), k = K + (i - n * (K4w - K));
        Ws[n * K4w + k] = 0.f;
    }
    // ---- zero chunk pads once (cp.async never writes words KC..KC4-1) ----
#pragma unroll
    for (int b = 0; b < NBUF; ++b)
        for (int i = tid; i < TR; i += THREADS)
#pragma unroll
            for (int p = KC; p < KC4; ++p) Xb[b][i * KC4 + p] = 0.f;

    float breg[C];
#pragma unroll
    for (int j = 0; j < C; ++j) breg[j] = bias[tx + LANES * j];

    const ulonglong2* wb = reinterpret_cast<const ulonglong2*>(Ws + (size_t)tx * K4w);
    const ulonglong2* xbp[NBUF];
#pragma unroll
    for (int b = 0; b < NBUF; ++b)
        xbp[b] = reinterpret_cast<const ulonglong2*>(Xb[b] + (size_t)ty * KC4);
    constexpr int WSTEP = LANES * K4w / 4;
    constexpr int XSTEP = G * KC4 / 4;

    const float4* X4 = reinterpret_cast<const float4*>(X1);
    constexpr int KV = KC / 4;               // float4 per row per chunk

    const int ntiles = (M + TR - 1) / TR;
    for (int tile = blockIdx.x; tile < ntiles; tile += gridDim.x) {
        const int row0 = tile * TR;
        __syncthreads();   // bufs free (prev tile fully computed), W staged

        // ---- stage chunk 0 ----
        if (CONCAT) {
            const float4* G4 = reinterpret_cast<const float4*>(X2);
            for (int u = tid; u < TR * 17; u += THREADS) {
                int r = u / 17, q = u - r * 17;
                int gr = row0 + r;
                if (q == 16) {
                    float a0 = 0.f, a1 = 0.f;
                    if (gr < M) { a0 = X1[gr * 2]; a1 = X1[gr * 2 + 1]; }
                    Xb[0][r * KC4 + 0] = a0;
                    Xb[0][r * KC4 + 1] = a1;
                } else {
                    float4 v = make_float4(0.f, 0.f, 0.f, 0.f);
                    if (gr < M) v = G4[(size_t)gr * 16 + q];
                    int c0 = 2 + 4 * q;
                    Xb[0][r * KC4 + c0]     = v.x;
                    Xb[0][r * KC4 + c0 + 1] = v.y;
                    Xb[0][r * KC4 + c0 + 2] = v.z;
                    Xb[0][r * KC4 + c0 + 3] = v.w;
                }
            }
        } else {
            for (int i = tid; i < TR * KV; i += THREADS) {
                int r = i / KV, c4 = i - r * KV;
                int gr = row0 + r;
                uint32_t dst = smem_u32(Xb[0] + r * KC4 + 4 * c4);
                const float4* src = X4 + (size_t)(gr < M ? gr : 0) * (K / 4) + c4;
                CP_ASYNC16(dst, src, (gr < M) ? 16 : 0);
            }
            CP_COMMIT();
        }

        u64 acc[R][C];
#pragma unroll
        for (int i = 0; i < R; ++i)
#pragma unroll
            for (int j = 0; j < C; ++j) acc[i][j] = 0ull;

#pragma unroll
        for (int cch = 0; cch < SPLIT; ++cch) {
            // prefetch next chunk into the other buffer
            if (SPLIT > 1 && cch + 1 < SPLIT) {
                const int nb = (cch + 1) & 1;
                for (int i = tid; i < TR * KV; i += THREADS) {
                    int r = i / KV, c4 = i - r * KV;
                    int gr = row0 + r;
                    uint32_t dst = smem_u32(Xb[nb] + r * KC4 + 4 * c4);
                    const float4* src = X4 + (size_t)(gr < M ? gr : 0) * (K / 4)
                                      + (cch + 1) * KV + c4;
                    CP_ASYNC16(dst, src, (gr < M) ? 16 : 0);
                }
                CP_COMMIT();
                cp_wait<1>();   // current chunk landed; next still in flight
            } else if (!CONCAT) {
                cp_wait<0>();   // last chunk landed
            }
            __syncthreads();    // all threads' data visible

            const ulonglong2* xb = xbp[cch & 1];
            const int goff = cch * (KC / 4);
#pragma unroll 1
            for (int g = 0; g < NG; ++g) {
                ulonglong2 w[C];
#pragma unroll
                for (int j = 0; j < C; ++j) w[j] = wb[goff + g + j * WSTEP];
#pragma unroll
                for (int i = 0; i < R; ++i) {
                    ulonglong2 a = xb[g + i * XSTEP];   // warp-broadcast
#pragma unroll
                    for (int j = 0; j < C; ++j) {
                        FMA2(acc[i][j], a.x, w[j].x);
                        FMA2(acc[i][j], a.y, w[j].y);
                    }
                }
            }
            if (SPLIT > 1 && cch + 1 < SPLIT)
                __syncthreads();   // buf[cch&1] free before refill at cch+2
        }

        // ---- epilogue (registers + shfl only) ----
        float val[R][C];
#pragma unroll
        for (int i = 0; i < R; ++i)
#pragma unroll
            for (int j = 0; j < C; ++j) {
                float lo, hi;
                UNPACK2(lo, hi, acc[i][j]);
                val[i][j] = lo + hi + breg[j];
            }

        if (RELU) {
#pragma unroll
            for (int i = 0; i < R; ++i) {
                int gr = row0 + ty + G * i;
                if (gr < M) {
#pragma unroll
                    for (int j = 0; j < C; ++j)
                        Y[(size_t)gr * N + tx + LANES * j] = fmaxf(val[i][j], 0.f);
                }
            }
        } else {   // L2N: each row lives in one warp
#pragma unroll
            for (int i = 0; i < R; ++i) {
                float s = val[i][0] * val[i][0] + val[i][1] * val[i][1]
                        + val[i][2] * val[i][2] + val[i][3] * val[i][3];
#pragma unroll
                for (int o = 16; o > 0; o >>= 1)
                    s += __shfl_xor_sync(0xffffffffu, s, o);
                float scale = 1.0f / fmaxf(sqrtf(s), 1e-12f);
                int gr = row0 + ty + G * i;
                if (gr < M) {
#pragma unroll
                    for (int j = 0; j < C; ++j)
                        Y[(size_t)gr * 128 + tx + 32 * j] = val[i][j] * scale;
                }
            }
        }
    }
}

// ---------------------------------------------------------------------------
// Segment boundaries from sorted seg_ids (users with no interactions -> [0,0))
// ---------------------------------------------------------------------------
__global__ void bounds_init_kernel(int* __restrict__ s, int* __restrict__ e, int n)
{
    int i = blockIdx.x * blockDim.x + threadIdx.x;
    if (i < n) { s[i] = 0; e[i] = 0; }
}

__global__ void bounds_kernel(const int* __restrict__ seg, int n,
                              int* __restrict__ s, int* __restrict__ e)
{
    int i = blockIdx.x * blockDim.x + threadIdx.x;
    if (i >= n) return;
    int id = seg[i];
    if (i == 0 || seg[i - 1] != id) s[id] = i;
    if (i == n - 1 || seg[i + 1] != id) e[id] = i + 1;
}

// ---------------------------------------------------------------------------
// One warp per user: fused[u] = concat(gcn_user_emb[users[u]], mean(item_emb))
// ---------------------------------------------------------------------------
__global__ void hist_kernel(const float* __restrict__ item_emb,
                            const int* __restrict__ item_idx,
                            const int* __restrict__ sa,
                            const int* __restrict__ ea,
                            const float* __restrict__ gue,
                            const int* __restrict__ users,
                            float* __restrict__ fused, int n_users)
{
    int w = (blockIdx.x * blockDim.x + threadIdx.x) >> 5;
    int lane = threadIdx.x & 31;
    if (w >= n_users) return;

    int uu = users[w];

    if (lane < 16) {
        float4 g = reinterpret_cast<const float4*>(gue + (size_t)uu * GCN)[lane];
        reinterpret_cast<float4*>(fused + (size_t)w * (GCN + TOW))[lane] = g;
    }

    int s = sa[uu], e = ea[uu];
    const float4* emb4 = reinterpret_cast<const float4*>(item_emb);

    float4 acc = make_float4(0.f, 0.f, 0.f, 0.f);
    int j = s;
    for (; j + 4 <= e; j += 4) {
        int i0 = item_idx[j], i1 = item_idx[j + 1], i2 = item_idx[j + 2], i3 = item_idx[j + 3];
        float4 v0 = emb4[(size_t)i0 * 32 + lane];
        float4 v1 = emb4[(size_t)i1 * 32 + lane];
        float4 v2 = emb4[(size_t)i2 * 32 + lane];
        float4 v3 = emb4[(size_t)i3 * 32 + lane];
        acc.x += (v0.x + v1.x) + (v2.x + v3.x);
        acc.y += (v0.y + v1.y) + (v2.y + v3.y);
        acc.z += (v0.z + v1.z) + (v2.z + v3.z);
        acc.w += (v0.w + v1.w) + (v2.w + v3.w);
    }
    for (; j < e; ++j) {
        int it = item_idx[j];
        float4 v = emb4[(size_t)it * 32 + lane];
        acc.x += v.x; acc.y += v.y; acc.z += v.z; acc.w += v.w;
    }
    float inv = 1.0f / fmaxf((float)(e - s), 1.0f);
    float4 m = make_float4(acc.x * inv, acc.y * inv, acc.z * inv, acc.w * inv);
    reinterpret_cast<float4*>(fused + (size_t)w * (GCN + TOW) + GCN)[lane] = m;
}

// ---------------------------------------------------------------------------
extern "C" void kernel_launch(void* const* d_in, const int* in_sizes, int n_in,
                              void* d_out, int out_size)
{
    const float* item_feat    = (const float*)d_in[0];
    const float* gcn_item_emb = (const float*)d_in[1];
    const float* gcn_user_emb = (const float*)d_in[2];
    const float* Wi1 = (const float*)d_in[3];
    const float* bi1 = (const float*)d_in[4];
    const float* Wi2 = (const float*)d_in[5];
    const float* bi2 = (const float*)d_in[6];
    const float* Wu1 = (const float*)d_in[7];
    const float* bu1 = (const float*)d_in[8];
    const float* Wu2 = (const float*)d_in[9];
    const float* bu2 = (const float*)d_in[10];
    const int* item_idx = (const int*)d_in[11];
    const int* seg_ids  = (const int*)d_in[12];
    const int* users    = (const int*)d_in[13];
    float* out = (float*)d_out;

    float *item_emb, *H, *fused;
    int *st, *en;
    cudaGetSymbolAddress((void**)&item_emb, g_item_emb);
    cudaGetSymbolAddress((void**)&H, g_H);
    cudaGetSymbolAddress((void**)&fused, g_fused);
    cudaGetSymbolAddress((void**)&st, g_start);
    cudaGetSymbolAddress((void**)&en, g_end);

    // instantiations (512 threads):
    //  i1: K=66  N=256 LANES=64 SPLIT=1 CONCAT  TR=64  KC4=68
    //  l2: K=256 N=128 LANES=32 SPLIT=4 L2N     TR=128 KC=64 KC4=68, 2 bufs
    //  u1: K=192 N=256 LANES=64 SPLIT=4 RELU    TR=64  KC=48 KC4=52, 2 bufs
    const int smem_i1 = (256 * PadK<66>::value  + 1 * 64  * PadK<66>::value) * 4;  //  87,040
    const int smem_l2 = (128 * PadK<256>::value + 2 * 128 * PadK<64>::value) * 4;  // 202,752
    const int smem_u1 = (256 * PadK<192>::value + 2 * 64  * PadK<48>::value) * 4;  // 227,328

    cudaFuncSetAttribute((const void*)gemm_kernel<66, 256, 64, 1, true, false, true>,
                         cudaFuncAttributeMaxDynamicSharedMemorySize, smem_i1);
    cudaFuncSetAttribute((const void*)gemm_kernel<256, 128, 32, 4, false, true, false>,
                         cudaFuncAttributeMaxDynamicSharedMemorySize, smem_l2);
    cudaFuncSetAttribute((const void*)gemm_kernel<192, 256, 64, 4, true, false, false>,
                         cudaFuncAttributeMaxDynamicSharedMemorySize, smem_u1);

    const int GRID = 152;   // persistent, 1 CTA per SM

    // 1) item L1: H = relu(concat(item_feat, gcn_item_emb) @ Wi1 + bi1)
    gemm_kernel<66, 256, 64, 1, true, false, true><<<GRID, 512, smem_i1>>>(
        item_feat, 2, gcn_item_emb, Wi1, bi1, H, N_ITEMS);

    // 2) item L2 + L2 norm -> item_emb
    gemm_kernel<256, 128, 32, 4, false, true, false><<<GRID, 512, smem_l2>>>(
        H, 256, H, Wi2, bi2, item_emb, N_ITEMS);

    // 3) segment boundaries
    bounds_init_kernel<<<(N_USERS + 255) / 256, 256>>>(st, en, N_USERS);
    bounds_kernel<<<(N_INTER + 255) / 256, 256>>>(seg_ids, N_INTER, st, en);

    // 4) ragged gather + mean -> fused
    hist_kernel<<<(N_USERS * 32 + 255) / 256, 256>>>(
        item_emb, item_idx, st, en, gcn_user_emb, users, fused, N_USERS);

    // 5) user L1
    gemm_kernel<192, 256, 64, 4, true, false, false><<<GRID, 512, smem_u1>>>(
        fused, 192, fused, Wu1, bu1, H, N_USERS);

    // 6) user L2 + L2 norm -> output
    gemm_kernel<256, 128, 32, 4, false, true, false><<<GRID, 512, smem_l2>>>(
        H, 256, H, Wu2, bu2, out, N_USERS);
}